// round 1
// baseline (speedup 1.0000x reference)
#include <cuda_runtime.h>
#include <math.h>

// Problem constants (static per metadata)
#define BATCH 2
#define NH    12
#define HD    64          // head dim
#define DIM   768
#define QT    8
#define QH_   14
#define QW    14
#define SEQ   1568        // 8*14*14, Q == K
#define MROWS 3136        // BATCH*SEQ

// ---------------- scratch (__device__ globals; no allocation allowed) ----------
__device__ float g_qh[BATCH*NH*SEQ*HD];     // [b,n,q,c]
__device__ float g_kh[BATCH*NH*SEQ*HD];     // [b,n,k,c]
__device__ float g_vh[BATCH*NH*SEQ*HD];     // [b,n,k,c]
__device__ float g_attn[BATCH*SEQ*DIM];     // [b,q,n*64+c]
__device__ float g_rt[BATCH*NH*SEQ*QT];     // [bnq, kt]
__device__ float g_rh[BATCH*NH*SEQ*QH_];    // [bnq, kh]
__device__ float g_rw[BATCH*NH*SEQ*QW];     // [bnq, kw]

// ---------------- GEMM: C[M,768] = A[M,768] * W[768,768]^T + bias -------------
// headMode=1: scatter C[m, o] -> dst[((b*NH+n)*SEQ + pos)*64 + c]
// headMode=0: dst[m*768 + o]
__global__ __launch_bounds__(256)
void gemm_nt_bias(const float* __restrict__ A, const float* __restrict__ W,
                  const float* __restrict__ bias, float* __restrict__ dst,
                  int headMode)
{
    __shared__ float As[64][17];
    __shared__ float Ws[64][17];
    const int tid = threadIdx.x;
    const int tx = tid & 15;
    const int ty = tid >> 4;
    const int rowBlk = blockIdx.y * 64;
    const int colBlk = blockIdx.x * 64;

    float acc[4][4] = {};

    for (int k0 = 0; k0 < DIM; k0 += 16) {
        #pragma unroll
        for (int i = 0; i < 4; i++) {
            int idx = i * 256 + tid;        // 0..1023
            int r = idx >> 4, c = idx & 15;
            As[r][c] = A[(size_t)(rowBlk + r) * DIM + k0 + c];
            Ws[r][c] = W[(size_t)(colBlk + r) * DIM + k0 + c];
        }
        __syncthreads();
        #pragma unroll
        for (int kk = 0; kk < 16; kk++) {
            float a[4], b[4];
            #pragma unroll
            for (int i = 0; i < 4; i++) a[i] = As[ty * 4 + i][kk];
            #pragma unroll
            for (int j = 0; j < 4; j++) b[j] = Ws[tx * 4 + j][kk];
            #pragma unroll
            for (int i = 0; i < 4; i++)
                #pragma unroll
                for (int j = 0; j < 4; j++)
                    acc[i][j] += a[i] * b[j];
        }
        __syncthreads();
    }

    #pragma unroll
    for (int i = 0; i < 4; i++) {
        int m = rowBlk + ty * 4 + i;
        #pragma unroll
        for (int j = 0; j < 4; j++) {
            int o = colBlk + tx * 4 + j;
            float v = acc[i][j] + bias[o];
            if (headMode) {
                int b = m / SEQ;
                int pos = m - b * SEQ;
                int n = o >> 6, c = o & 63;
                dst[(((size_t)(b * NH + n)) * SEQ + pos) * HD + c] = v;
            } else {
                dst[(size_t)m * DIM + o] = v;
            }
        }
    }
}

// ---------------- rel-pos einsums --------------------------------------------
// For q_size==k_size: dist_t = t - kt + (QT-1); dist_hw = i - j + 13
__global__ __launch_bounds__(64)
void relpos_kernel(const float* __restrict__ qh,
                   const float* __restrict__ rpt,
                   const float* __restrict__ rph,
                   const float* __restrict__ rpw,
                   float* __restrict__ rel_t,
                   float* __restrict__ rel_h,
                   float* __restrict__ rel_w)
{
    const int bnq = blockIdx.x;          // (b*NH+n)*SEQ + q
    const int q = bnq % SEQ;

    __shared__ __align__(16) float qs[HD];
    qs[threadIdx.x] = qh[(size_t)bnq * HD + threadIdx.x];
    __syncthreads();

    const int t = q / (QH_ * QW);
    const int rem = q - t * (QH_ * QW);
    const int h = rem / QW;
    const int w = rem - h * QW;

    const int j = threadIdx.x;
    if (j < QT + QH_ + QW) {             // 36 outputs
        const float* r;
        float* dstp;
        if (j < QT) {
            r = rpt + (size_t)(t - j + QT - 1) * HD;
            dstp = rel_t + (size_t)bnq * QT + j;
        } else if (j < QT + QH_) {
            int kh = j - QT;
            r = rph + (size_t)(h - kh + QH_ - 1) * HD;
            dstp = rel_h + (size_t)bnq * QH_ + kh;
        } else {
            int kw = j - QT - QH_;
            r = rpw + (size_t)(w - kw + QW - 1) * HD;
            dstp = rel_w + (size_t)bnq * QW + kw;
        }
        float acc = 0.f;
        #pragma unroll
        for (int c = 0; c < HD; c++) acc += qs[c] * r[c];
        *dstp = acc;
    }
}

// ---------------- attention: one block per (b,n,q) ----------------------------
__global__ __launch_bounds__(128)
void attention_kernel(const float* __restrict__ qh,
                      const float* __restrict__ kh,
                      const float* __restrict__ vh,
                      const float* __restrict__ rel_t,
                      const float* __restrict__ rel_h,
                      const float* __restrict__ rel_w,
                      float* __restrict__ attn_out)
{
    const int q = blockIdx.x;
    const int n = blockIdx.y;
    const int b = blockIdx.z;
    const int bn = b * NH + n;
    const size_t bnq = (size_t)bn * SEQ + q;
    const int tid = threadIdx.x;

    __shared__ __align__(16) float q_s[HD];
    __shared__ float sc[SEQ];
    __shared__ float bt[QT], bh[QH_], bw[QW];
    __shared__ float s_red[4];
    __shared__ float s_bcast;
    __shared__ float partial[128];

    if (tid < HD) q_s[tid] = qh[bnq * HD + tid];
    if (tid < QT)  bt[tid] = rel_t[bnq * QT + tid];
    if (tid < QH_) bh[tid] = rel_h[bnq * QH_ + tid];
    if (tid < QW)  bw[tid] = rel_w[bnq * QW + tid];
    __syncthreads();

    const float scale = 0.125f;  // 1/sqrt(64)
    const float4* q4 = (const float4*)q_s;
    const float* kbase = kh + (size_t)bn * SEQ * HD;

    // scores
    for (int kk = tid; kk < SEQ; kk += 128) {
        const float4* k4 = (const float4*)(kbase + (size_t)kk * HD);
        float acc = 0.f;
        #pragma unroll
        for (int i = 0; i < 16; i++) {
            float4 kv = k4[i];
            float4 qv = q4[i];
            acc += kv.x * qv.x + kv.y * qv.y + kv.z * qv.z + kv.w * qv.w;
        }
        int kt = kk / (QH_ * QW);
        int rem = kk - kt * (QH_ * QW);
        int khh = rem / QW;
        int kww = rem - khh * QW;
        sc[kk] = acc * scale + bt[kt] + bh[khh] + bw[kww];
    }

    const int lane = tid & 31, wid = tid >> 5;

    // max-reduce
    float lm = -1e30f;
    for (int kk = tid; kk < SEQ; kk += 128) lm = fmaxf(lm, sc[kk]);
    #pragma unroll
    for (int o = 16; o; o >>= 1) lm = fmaxf(lm, __shfl_xor_sync(0xffffffffu, lm, o));
    if (lane == 0) s_red[wid] = lm;
    __syncthreads();
    if (tid == 0)
        s_bcast = fmaxf(fmaxf(s_red[0], s_red[1]), fmaxf(s_red[2], s_red[3]));
    __syncthreads();
    const float mx = s_bcast;

    // exp + sum-reduce
    float ls = 0.f;
    for (int kk = tid; kk < SEQ; kk += 128) {
        float e = __expf(sc[kk] - mx);
        sc[kk] = e;
        ls += e;
    }
    #pragma unroll
    for (int o = 16; o; o >>= 1) ls += __shfl_xor_sync(0xffffffffu, ls, o);
    if (lane == 0) s_red[wid] = ls;
    __syncthreads();
    if (tid == 0)
        s_bcast = 1.f / (s_red[0] + s_red[1] + s_red[2] + s_red[3]);
    __syncthreads();
    const float inv = s_bcast;

    // AV: thread = channel (c = tid&63), two k-halves
    const int c = tid & 63;
    const int half = tid >> 6;
    const float* vb = vh + (size_t)bn * SEQ * HD + c;
    float acc = 0.f;
    const int k0 = half * (SEQ / 2), k1 = k0 + (SEQ / 2);
    #pragma unroll 8
    for (int kk = k0; kk < k1; kk++)
        acc += sc[kk] * vb[(size_t)kk * HD];

    partial[tid] = acc;
    __syncthreads();
    if (tid < HD) {
        float v = (partial[tid] + partial[tid + 64]) * inv;
        attn_out[((size_t)b * SEQ + q) * DIM + n * HD + tid] = v;
    }
}

// ---------------- launch ------------------------------------------------------
extern "C" void kernel_launch(void* const* d_in, const int* in_sizes, int n_in,
                              void* d_out, int out_size)
{
    (void)in_sizes; (void)n_in; (void)out_size;
    const float* q   = (const float*)d_in[0];
    const float* k   = (const float*)d_in[1];
    const float* Wq  = (const float*)d_in[2];
    const float* bq  = (const float*)d_in[3];
    const float* Wk  = (const float*)d_in[4];
    const float* bk  = (const float*)d_in[5];
    const float* Wv  = (const float*)d_in[6];
    const float* bv  = (const float*)d_in[7];
    const float* Wo  = (const float*)d_in[8];
    const float* bo  = (const float*)d_in[9];
    const float* rpt = (const float*)d_in[10];
    const float* rph = (const float*)d_in[11];
    const float* rpw = (const float*)d_in[12];
    float* out = (float*)d_out;

    float *p_qh, *p_kh, *p_vh, *p_attn, *p_rt, *p_rh, *p_rw;
    cudaGetSymbolAddress((void**)&p_qh,   g_qh);
    cudaGetSymbolAddress((void**)&p_kh,   g_kh);
    cudaGetSymbolAddress((void**)&p_vh,   g_vh);
    cudaGetSymbolAddress((void**)&p_attn, g_attn);
    cudaGetSymbolAddress((void**)&p_rt,   g_rt);
    cudaGetSymbolAddress((void**)&p_rh,   g_rh);
    cudaGetSymbolAddress((void**)&p_rw,   g_rw);

    dim3 gemmGrid(DIM / 64, MROWS / 64);     // 12 x 49
    gemm_nt_bias<<<gemmGrid, 256>>>(q, Wq, bq, p_qh, 1);
    gemm_nt_bias<<<gemmGrid, 256>>>(k, Wk, bk, p_kh, 1);
    gemm_nt_bias<<<gemmGrid, 256>>>(k, Wv, bv, p_vh, 1);

    relpos_kernel<<<BATCH * NH * SEQ, 64>>>(p_qh, rpt, rph, rpw, p_rt, p_rh, p_rw);

    dim3 attnGrid(SEQ, NH, BATCH);
    attention_kernel<<<attnGrid, 128>>>(p_qh, p_kh, p_vh, p_rt, p_rh, p_rw, p_attn);

    gemm_nt_bias<<<gemmGrid, 256>>>(p_attn, Wo, bo, out, 0);
}

// round 2
// speedup vs baseline: 5.5139x; 5.5139x over previous
#include <cuda_runtime.h>
#include <math.h>

#define BATCH 2
#define NH    12
#define HD    64
#define DIM   768
#define QT    8
#define QHH   14
#define QW    14
#define SEQ   1568
#define KSEQ  1600          // padded to 25*64
#define MROWS 3136          // BATCH*SEQ

// ---------------- scratch ------------------------------------------------------
__device__ float g_qh[BATCH*NH*KSEQ*HD];    // [b,n,q,c] (pad rows unused)
__device__ float g_kh[BATCH*NH*KSEQ*HD];    // pad rows stay zero
__device__ float g_vh[BATCH*NH*KSEQ*HD];    // pad rows stay zero
__device__ float g_attn[MROWS*DIM];

// ---------------- GEMM: C[M,768] = A[M,768]*W[768,768]^T + bias ---------------
// 128x128 tile, 256 threads, 8x8 micro (split 64-halves)
__global__ __launch_bounds__(256)
void gemm128(const float* __restrict__ A, const float* __restrict__ W,
             const float* __restrict__ bias, float* __restrict__ dst,
             int M, int headMode)
{
    __shared__ float As[16][132];
    __shared__ float Bs[16][132];
    const int tid = threadIdx.x;
    const int tx = tid & 15;
    const int ty = tid >> 4;
    const int rowBlk = blockIdx.y * 128;
    const int colBlk = blockIdx.x * 128;

    // load indices
    const int lr  = tid >> 2;        // 0..63
    const int kq  = tid & 3;         // 0..3 -> k = kq*4..kq*4+3

    float acc[8][8];
    #pragma unroll
    for (int i = 0; i < 8; i++)
        #pragma unroll
        for (int j = 0; j < 8; j++) acc[i][j] = 0.f;

    for (int k0 = 0; k0 < DIM; k0 += 16) {
        // ---- load A tile (transposed to As[k][m]) ----
        {
            int r0 = rowBlk + lr, r1 = rowBlk + lr + 64;
            float4 a0 = make_float4(0,0,0,0), a1 = make_float4(0,0,0,0);
            if (r0 < M) a0 = *(const float4*)(A + (size_t)r0 * DIM + k0 + kq*4);
            if (r1 < M) a1 = *(const float4*)(A + (size_t)r1 * DIM + k0 + kq*4);
            As[kq*4+0][lr]    = a0.x; As[kq*4+1][lr]    = a0.y;
            As[kq*4+2][lr]    = a0.z; As[kq*4+3][lr]    = a0.w;
            As[kq*4+0][lr+64] = a1.x; As[kq*4+1][lr+64] = a1.y;
            As[kq*4+2][lr+64] = a1.z; As[kq*4+3][lr+64] = a1.w;
            // W rows are output cols, always in range (N=768)
            int c0 = colBlk + lr, c1 = colBlk + lr + 64;
            float4 b0 = *(const float4*)(W + (size_t)c0 * DIM + k0 + kq*4);
            float4 b1 = *(const float4*)(W + (size_t)c1 * DIM + k0 + kq*4);
            Bs[kq*4+0][lr]    = b0.x; Bs[kq*4+1][lr]    = b0.y;
            Bs[kq*4+2][lr]    = b0.z; Bs[kq*4+3][lr]    = b0.w;
            Bs[kq*4+0][lr+64] = b1.x; Bs[kq*4+1][lr+64] = b1.y;
            Bs[kq*4+2][lr+64] = b1.z; Bs[kq*4+3][lr+64] = b1.w;
        }
        __syncthreads();

        #pragma unroll
        for (int kk = 0; kk < 16; kk++) {
            float4 a0 = *(const float4*)&As[kk][ty*4];
            float4 a1 = *(const float4*)&As[kk][64 + ty*4];
            float4 b0 = *(const float4*)&Bs[kk][tx*4];
            float4 b1 = *(const float4*)&Bs[kk][64 + tx*4];
            float av[8] = {a0.x,a0.y,a0.z,a0.w,a1.x,a1.y,a1.z,a1.w};
            float bv[8] = {b0.x,b0.y,b0.z,b0.w,b1.x,b1.y,b1.z,b1.w};
            #pragma unroll
            for (int i = 0; i < 8; i++)
                #pragma unroll
                for (int j = 0; j < 8; j++)
                    acc[i][j] += av[i] * bv[j];
        }
        __syncthreads();
    }

    // epilogue
    #pragma unroll
    for (int ih = 0; ih < 2; ih++) {
        #pragma unroll
        for (int i = 0; i < 4; i++) {
            int m = rowBlk + ih*64 + ty*4 + i;
            if (m >= M) continue;
            #pragma unroll
            for (int jh = 0; jh < 2; jh++) {
                #pragma unroll
                for (int j = 0; j < 4; j++) {
                    int o = colBlk + jh*64 + tx*4 + j;
                    float v = acc[ih*4+i][jh*4+j] + bias[o];
                    if (headMode) {
                        int b = m / SEQ;
                        int pos = m - b * SEQ;
                        int n = o >> 6, c = o & 63;
                        dst[(((size_t)(b*NH + n)) * KSEQ + pos) * HD + c] = v;
                    } else {
                        dst[(size_t)m * DIM + o] = v;
                    }
                }
            }
        }
    }
}

// ---------------- fused relpos + flash attention ------------------------------
// grid (25, 12, 2), 256 threads, dynamic smem
#define PADW 68

__global__ __launch_bounds__(256)
void attn_kernel(const float* __restrict__ qh, const float* __restrict__ kh,
                 const float* __restrict__ vh,
                 const float* __restrict__ rpt, const float* __restrict__ rph,
                 const float* __restrict__ rpw,
                 float* __restrict__ out)
{
    extern __shared__ float sm[];
    float* Qs  = sm;                 // [c=64][q=64] stride PADW
    float* Ks  = Qs + 64*PADW;       // [c=64][k=64]
    float* Vs  = Ks + 64*PADW;       // [k=64][c=64]
    float* Ps  = Vs + 64*PADW;       // [q=64][k=64]
    float* sbt = Ps + 64*PADW;       // [q][8]
    float* sbh = sbt + 64*8;         // [q][14]
    float* sbw = sbh + 64*14;        // [q][14]

    const int tid = threadIdx.x;
    const int tx = tid & 15;
    const int ty = tid >> 4;
    const int qblk = blockIdx.x;
    const int n = blockIdx.y;
    const int b = blockIdx.z;
    const int bn = b * NH + n;
    const int qbase = qblk * 64;

    const float* qbaseP = qh + (size_t)bn * KSEQ * HD;
    const float* kbaseP = kh + (size_t)bn * KSEQ * HD;
    const float* vbaseP = vh + (size_t)bn * KSEQ * HD;

    // ---- load Q tile transposed ----
    {
        const int c0 = tx * 4;
        #pragma unroll
        for (int it = 0; it < 4; it++) {
            int lq = ty + 16 * it;
            int gq = qbase + lq;
            float4 v = make_float4(0,0,0,0);
            if (gq < SEQ) v = *(const float4*)(qbaseP + (size_t)gq * HD + c0);
            Qs[(c0+0)*PADW + lq] = v.x;
            Qs[(c0+1)*PADW + lq] = v.y;
            Qs[(c0+2)*PADW + lq] = v.z;
            Qs[(c0+3)*PADW + lq] = v.w;
        }
    }
    __syncthreads();

    // ---- bias tables: sbt/sbh/sbw per local q ----
    for (int idx = tid; idx < 64 * 36; idx += 256) {
        int lq = idx & 63;
        int j  = idx >> 6;                  // 0..35
        int gq = qbase + lq;
        if (gq >= SEQ) gq = SEQ - 1;
        int t = gq / (QHH * QW);
        int rem = gq - t * (QHH * QW);
        int h = rem / QW;
        int w = rem - h * QW;
        const float* r;
        float* dstp;
        if (j < 8)       { r = rpt + (size_t)(t - j + QT - 1) * HD;        dstp = &sbt[lq*8 + j]; }
        else if (j < 22) { int kk = j - 8;  r = rph + (size_t)(h - kk + QHH - 1) * HD; dstp = &sbh[lq*14 + kk]; }
        else             { int kk = j - 22; r = rpw + (size_t)(w - kk + QW  - 1) * HD; dstp = &sbw[lq*14 + kk]; }
        float acc = 0.f;
        #pragma unroll
        for (int c = 0; c < HD; c++) acc += Qs[c*PADW + lq] * r[c];
        *dstp = acc;
    }
    __syncthreads();

    // ---- online softmax state ----
    float accO[4][4];
    #pragma unroll
    for (int i = 0; i < 4; i++)
        #pragma unroll
        for (int j = 0; j < 4; j++) accO[i][j] = 0.f;
    float mrow[4] = {-1e30f, -1e30f, -1e30f, -1e30f};
    float lrow[4] = {0.f, 0.f, 0.f, 0.f};

    const float scale = 0.125f;

    for (int kb = 0; kb < KSEQ; kb += 64) {
        // ---- load K (transposed) and V (direct) tiles ----
        {
            const int c0 = tx * 4;
            #pragma unroll
            for (int it = 0; it < 4; it++) {
                int lk = ty + 16 * it;
                float4 kv = *(const float4*)(kbaseP + (size_t)(kb + lk) * HD + c0);
                Ks[(c0+0)*PADW + lk] = kv.x;
                Ks[(c0+1)*PADW + lk] = kv.y;
                Ks[(c0+2)*PADW + lk] = kv.z;
                Ks[(c0+3)*PADW + lk] = kv.w;
                float4 vv = *(const float4*)(vbaseP + (size_t)(kb + lk) * HD + c0);
                *(float4*)&Vs[lk*PADW + c0] = vv;
            }
        }
        __syncthreads();

        // ---- S = Q K^T (outer product over c) ----
        float s[4][4];
        #pragma unroll
        for (int i = 0; i < 4; i++)
            #pragma unroll
            for (int j = 0; j < 4; j++) s[i][j] = 0.f;
        #pragma unroll 8
        for (int c = 0; c < 64; c++) {
            float4 a = *(const float4*)&Qs[c*PADW + ty*4];
            float4 bk = *(const float4*)&Ks[c*PADW + tx*4];
            float av[4] = {a.x, a.y, a.z, a.w};
            float bv[4] = {bk.x, bk.y, bk.z, bk.w};
            #pragma unroll
            for (int i = 0; i < 4; i++)
                #pragma unroll
                for (int j = 0; j < 4; j++)
                    s[i][j] += av[i] * bv[j];
        }

        // ---- scale + bias + mask ----
        #pragma unroll
        for (int j = 0; j < 4; j++) {
            int gk = kb + tx*4 + j;
            if (gk < SEQ) {
                int kt = gk / (QHH * QW);
                int rem = gk - kt * (QHH * QW);
                int khh = rem / QW;
                int kww = rem - khh * QW;
                #pragma unroll
                for (int i = 0; i < 4; i++) {
                    int lq = ty*4 + i;
                    s[i][j] = s[i][j] * scale + sbt[lq*8 + kt] + sbh[lq*14 + khh] + sbw[lq*14 + kww];
                }
            } else {
                #pragma unroll
                for (int i = 0; i < 4; i++) s[i][j] = -1e30f;
            }
        }

        // ---- online softmax update ----
        #pragma unroll
        for (int i = 0; i < 4; i++) {
            float rm = fmaxf(fmaxf(s[i][0], s[i][1]), fmaxf(s[i][2], s[i][3]));
            #pragma unroll
            for (int off = 8; off; off >>= 1)
                rm = fmaxf(rm, __shfl_xor_sync(0xffffffffu, rm, off));
            float mnew = fmaxf(mrow[i], rm);
            float corr = __expf(mrow[i] - mnew);
            mrow[i] = mnew;
            lrow[i] *= corr;
            #pragma unroll
            for (int j = 0; j < 4; j++) accO[i][j] *= corr;
            float rs = 0.f;
            float p0 = __expf(s[i][0] - mnew);
            float p1 = __expf(s[i][1] - mnew);
            float p2 = __expf(s[i][2] - mnew);
            float p3 = __expf(s[i][3] - mnew);
            rs = p0 + p1 + p2 + p3;
            #pragma unroll
            for (int off = 8; off; off >>= 1)
                rs += __shfl_xor_sync(0xffffffffu, rs, off);
            lrow[i] += rs;
            *(float4*)&Ps[(ty*4+i)*PADW + tx*4] = make_float4(p0, p1, p2, p3);
        }
        __syncthreads();

        // ---- O += P V ----
        #pragma unroll 8
        for (int k = 0; k < 64; k++) {
            float4 bv4 = *(const float4*)&Vs[k*PADW + tx*4];
            float bv[4] = {bv4.x, bv4.y, bv4.z, bv4.w};
            float av[4];
            #pragma unroll
            for (int i = 0; i < 4; i++) av[i] = Ps[(ty*4+i)*PADW + k];
            #pragma unroll
            for (int i = 0; i < 4; i++)
                #pragma unroll
                for (int j = 0; j < 4; j++)
                    accO[i][j] += av[i] * bv[j];
        }
        __syncthreads();
    }

    // ---- write out: [b][q][n*64 + c] ----
    #pragma unroll
    for (int i = 0; i < 4; i++) {
        int gq = qbase + ty*4 + i;
        if (gq >= SEQ) continue;
        float inv = 1.f / lrow[i];
        float4 o = make_float4(accO[i][0]*inv, accO[i][1]*inv, accO[i][2]*inv, accO[i][3]*inv);
        *(float4*)(out + ((size_t)b * SEQ + gq) * DIM + n * HD + tx*4) = o;
    }
}

// ---------------- launch ------------------------------------------------------
extern "C" void kernel_launch(void* const* d_in, const int* in_sizes, int n_in,
                              void* d_out, int out_size)
{
    (void)in_sizes; (void)n_in; (void)out_size;
    const float* q   = (const float*)d_in[0];
    const float* k   = (const float*)d_in[1];
    const float* Wq  = (const float*)d_in[2];
    const float* bq  = (const float*)d_in[3];
    const float* Wk  = (const float*)d_in[4];
    const float* bk  = (const float*)d_in[5];
    const float* Wv  = (const float*)d_in[6];
    const float* bv  = (const float*)d_in[7];
    const float* Wo  = (const float*)d_in[8];
    const float* bo  = (const float*)d_in[9];
    const float* rpt = (const float*)d_in[10];
    const float* rph = (const float*)d_in[11];
    const float* rpw = (const float*)d_in[12];
    float* out = (float*)d_out;

    float *p_qh, *p_kh, *p_vh, *p_attn;
    cudaGetSymbolAddress((void**)&p_qh,   g_qh);
    cudaGetSymbolAddress((void**)&p_kh,   g_kh);
    cudaGetSymbolAddress((void**)&p_vh,   g_vh);
    cudaGetSymbolAddress((void**)&p_attn, g_attn);

    static int smem_set = 0;
    const int attn_smem = (4*64*PADW + 64*36) * 4;   // 78848 B
    if (!smem_set) {
        cudaFuncSetAttribute(attn_kernel,
                             cudaFuncAttributeMaxDynamicSharedMemorySize, attn_smem);
        smem_set = 1;
    }

    dim3 gemmGrid(DIM / 128, (MROWS + 127) / 128);   // 6 x 25
    gemm128<<<gemmGrid, 256>>>(q, Wq, bq, p_qh, MROWS, 1);
    gemm128<<<gemmGrid, 256>>>(k, Wk, bk, p_kh, MROWS, 1);
    gemm128<<<gemmGrid, 256>>>(k, Wv, bv, p_vh, MROWS, 1);

    dim3 attnGrid((SEQ + 63) / 64, NH, BATCH);       // 25 x 12 x 2
    attn_kernel<<<attnGrid, 256, attn_smem>>>(p_qh, p_kh, p_vh, rpt, rph, rpw, p_attn);

    gemm128<<<gemmGrid, 256>>>(p_attn, Wo, bo, out, MROWS, 0);
}

// round 4
// speedup vs baseline: 7.0755x; 1.2832x over previous
#include <cuda_runtime.h>
#include <cstdint>
#include <math.h>

#define BATCH 2
#define NH    12
#define HD    64
#define DIM   768
#define QT    8
#define QHH   14
#define QW    14
#define SEQ   1568
#define KSEQ  1600
#define MROWS 3136

// ---------------- scratch ------------------------------------------------------
__device__ float g_qh[BATCH*NH*KSEQ*HD];
__device__ float g_kh[BATCH*NH*KSEQ*HD];
__device__ float g_vh[BATCH*NH*KSEQ*HD];
__device__ float g_attn[MROWS*DIM];

// ---------------- mma.sync helpers --------------------------------------------
__device__ __forceinline__ uint32_t f2tf32(float x) {
    uint32_t r;
    asm("cvt.rna.tf32.f32 %0, %1;" : "=r"(r) : "f"(x));
    return r;
}
__device__ __forceinline__ void mma_tf32(float* c, const uint32_t* a, const uint32_t* b) {
    asm volatile(
        "mma.sync.aligned.m16n8k8.row.col.f32.tf32.tf32.f32 "
        "{%0,%1,%2,%3}, {%4,%5,%6,%7}, {%8,%9}, {%0,%1,%2,%3};"
        : "+f"(c[0]), "+f"(c[1]), "+f"(c[2]), "+f"(c[3])
        : "r"(a[0]), "r"(a[1]), "r"(a[2]), "r"(a[3]), "r"(b[0]), "r"(b[1]));
}

// ---------------- tf32 mma GEMM: C[M,768] = A*W^T + bias ----------------------
// CTA tile 128x128, 256 thr (8 warps, 2m x 4n), warp tile 64x32, K-chunk 32
#define KC 32
#define LDT 36                        // padded k-stride in words
#define EPI_PITCH 132
#define GEMM_SMEM (128 * EPI_PITCH * 4)   // 67584 >= 2*128*36*4=36864

__global__ __launch_bounds__(256)
void gemm_mma(const float* __restrict__ A, const float* __restrict__ W,
              const float* __restrict__ bias, float* __restrict__ dst,
              int M, int headMode)
{
    extern __shared__ float smf[];
    uint32_t* As = (uint32_t*)smf;                 // [128][36]
    uint32_t* Bs = As + 128 * LDT;                 // [128][36]

    const int tid = threadIdx.x;
    const int lane = tid & 31;
    const int wid = tid >> 5;
    const int wm = wid >> 2;          // 0..1
    const int wn = wid & 3;           // 0..3
    const int rowBlk = blockIdx.y * 128;
    const int colBlk = blockIdx.x * 128;

    float acc[4][4][4];
    #pragma unroll
    for (int mi = 0; mi < 4; mi++)
        #pragma unroll
        for (int ni = 0; ni < 4; ni++)
            #pragma unroll
            for (int e = 0; e < 4; e++) acc[mi][ni][e] = 0.f;

    // global load mapping
    const int lrow = tid >> 1;
    const int lc0 = (tid & 1) * 16;
    const bool avalid = (rowBlk + lrow) < M;
    const float* aptr = A + (size_t)(rowBlk + lrow) * DIM + lc0;
    const float* wptr = W + (size_t)(colBlk + lrow) * DIM + lc0;

    float4 ra[4], rb[4];
    #pragma unroll
    for (int i = 0; i < 4; i++) {
        ra[i] = avalid ? *(const float4*)(aptr + i * 4) : make_float4(0,0,0,0);
        rb[i] = *(const float4*)(wptr + i * 4);
    }

    const int NCH = DIM / KC;         // 24
    for (int ch = 0; ch < NCH; ch++) {
        if (ch > 0) __syncthreads();
        #pragma unroll
        for (int i = 0; i < 4; i++) {
            uint4 ua = make_uint4(f2tf32(ra[i].x), f2tf32(ra[i].y), f2tf32(ra[i].z), f2tf32(ra[i].w));
            uint4 ub = make_uint4(f2tf32(rb[i].x), f2tf32(rb[i].y), f2tf32(rb[i].z), f2tf32(rb[i].w));
            *(uint4*)&As[lrow * LDT + lc0 + i * 4] = ua;
            *(uint4*)&Bs[lrow * LDT + lc0 + i * 4] = ub;
        }
        __syncthreads();
        if (ch + 1 < NCH) {
            const int k0 = (ch + 1) * KC;
            #pragma unroll
            for (int i = 0; i < 4; i++) {
                ra[i] = avalid ? *(const float4*)(aptr + k0 + i * 4) : make_float4(0,0,0,0);
                rb[i] = *(const float4*)(wptr + k0 + i * 4);
            }
        }
        // compute: 4 k-steps of 8
        #pragma unroll
        for (int ks = 0; ks < 4; ks++) {
            const int c0 = ks * 8 + (lane & 3);
            uint32_t afr[4][4], bfr[4][2];
            #pragma unroll
            for (int mi = 0; mi < 4; mi++) {
                const int r = wm * 64 + mi * 16 + (lane >> 2);
                afr[mi][0] = As[r * LDT + c0];
                afr[mi][1] = As[(r + 8) * LDT + c0];
                afr[mi][2] = As[r * LDT + c0 + 4];
                afr[mi][3] = As[(r + 8) * LDT + c0 + 4];
            }
            #pragma unroll
            for (int ni = 0; ni < 4; ni++) {
                const int bn = wn * 32 + ni * 8 + (lane >> 2);
                bfr[ni][0] = Bs[bn * LDT + c0];
                bfr[ni][1] = Bs[bn * LDT + c0 + 4];
            }
            #pragma unroll
            for (int mi = 0; mi < 4; mi++)
                #pragma unroll
                for (int ni = 0; ni < 4; ni++)
                    mma_tf32(acc[mi][ni], afr[mi], bfr[ni]);
        }
    }
    __syncthreads();

    // ---- epilogue: regs -> smem (pitch 132) -> global with bias + scatter ----
    float* epi = smf;
    #pragma unroll
    for (int mi = 0; mi < 4; mi++) {
        const int r = wm * 64 + mi * 16 + (lane >> 2);
        #pragma unroll
        for (int ni = 0; ni < 4; ni++) {
            const int c = wn * 32 + ni * 8 + 2 * (lane & 3);
            *(float2*)&epi[r * EPI_PITCH + c]       = make_float2(acc[mi][ni][0], acc[mi][ni][1]);
            *(float2*)&epi[(r + 8) * EPI_PITCH + c] = make_float2(acc[mi][ni][2], acc[mi][ni][3]);
        }
    }
    __syncthreads();

    for (int it = tid; it < 128 * 32; it += 256) {
        const int m2 = it >> 5;
        const int gm = rowBlk + m2;
        if (gm >= M) continue;
        const int c4 = (it & 31) * 4;
        const float4 bv = *(const float4*)(bias + colBlk + c4);
        float4 v;
        v.x = epi[m2 * EPI_PITCH + c4 + 0] + bv.x;
        v.y = epi[m2 * EPI_PITCH + c4 + 1] + bv.y;
        v.z = epi[m2 * EPI_PITCH + c4 + 2] + bv.z;
        v.w = epi[m2 * EPI_PITCH + c4 + 3] + bv.w;
        const int o = colBlk + c4;
        if (headMode) {
            int b = gm / SEQ;
            int pos = gm - b * SEQ;
            int n = o >> 6, c = o & 63;
            *(float4*)(dst + (((size_t)(b * NH + n)) * KSEQ + pos) * HD + c) = v;
        } else {
            *(float4*)(dst + (size_t)gm * DIM + o) = v;
        }
    }
}

// ---------------- fused relpos + flash attention (unchanged, fp32) ------------
#define PADW 68

__global__ __launch_bounds__(256)
void attn_kernel(const float* __restrict__ qh, const float* __restrict__ kh,
                 const float* __restrict__ vh,
                 const float* __restrict__ rpt, const float* __restrict__ rph,
                 const float* __restrict__ rpw,
                 float* __restrict__ out)
{
    extern __shared__ float sm[];
    float* Qs  = sm;
    float* Ks  = Qs + 64*PADW;
    float* Vs  = Ks + 64*PADW;
    float* Ps  = Vs + 64*PADW;
    float* sbt = Ps + 64*PADW;
    float* sbh = sbt + 64*8;
    float* sbw = sbh + 64*14;

    const int tid = threadIdx.x;
    const int tx = tid & 15;
    const int ty = tid >> 4;
    const int qblk = blockIdx.x;
    const int n = blockIdx.y;
    const int b = blockIdx.z;
    const int bn = b * NH + n;
    const int qbase = qblk * 64;

    const float* qbaseP = qh + (size_t)bn * KSEQ * HD;
    const float* kbaseP = kh + (size_t)bn * KSEQ * HD;
    const float* vbaseP = vh + (size_t)bn * KSEQ * HD;

    {
        const int c0 = tx * 4;
        #pragma unroll
        for (int it = 0; it < 4; it++) {
            int lq = ty + 16 * it;
            int gq = qbase + lq;
            float4 v = make_float4(0,0,0,0);
            if (gq < SEQ) v = *(const float4*)(qbaseP + (size_t)gq * HD + c0);
            Qs[(c0+0)*PADW + lq] = v.x;
            Qs[(c0+1)*PADW + lq] = v.y;
            Qs[(c0+2)*PADW + lq] = v.z;
            Qs[(c0+3)*PADW + lq] = v.w;
        }
    }
    __syncthreads();

    for (int idx = tid; idx < 64 * 36; idx += 256) {
        int lq = idx & 63;
        int j  = idx >> 6;
        int gq = qbase + lq;
        if (gq >= SEQ) gq = SEQ - 1;
        int t = gq / (QHH * QW);
        int rem = gq - t * (QHH * QW);
        int h = rem / QW;
        int w = rem - h * QW;
        const float* r;
        float* dstp;
        if (j < 8)       { r = rpt + (size_t)(t - j + QT - 1) * HD;        dstp = &sbt[lq*8 + j]; }
        else if (j < 22) { int kk = j - 8;  r = rph + (size_t)(h - kk + QHH - 1) * HD; dstp = &sbh[lq*14 + kk]; }
        else             { int kk = j - 22; r = rpw + (size_t)(w - kk + QW  - 1) * HD; dstp = &sbw[lq*14 + kk]; }
        float acc = 0.f;
        #pragma unroll
        for (int c = 0; c < HD; c++) acc += Qs[c*PADW + lq] * r[c];
        *dstp = acc;
    }
    __syncthreads();

    float accO[4][4];
    #pragma unroll
    for (int i = 0; i < 4; i++)
        #pragma unroll
        for (int j = 0; j < 4; j++) accO[i][j] = 0.f;
    float mrow[4] = {-1e30f, -1e30f, -1e30f, -1e30f};
    float lrow[4] = {0.f, 0.f, 0.f, 0.f};

    const float scale = 0.125f;

    for (int kb = 0; kb < KSEQ; kb += 64) {
        {
            const int c0 = tx * 4;
            #pragma unroll
            for (int it = 0; it < 4; it++) {
                int lk = ty + 16 * it;
                float4 kv = *(const float4*)(kbaseP + (size_t)(kb + lk) * HD + c0);
                Ks[(c0+0)*PADW + lk] = kv.x;
                Ks[(c0+1)*PADW + lk] = kv.y;
                Ks[(c0+2)*PADW + lk] = kv.z;
                Ks[(c0+3)*PADW + lk] = kv.w;
                float4 vv = *(const float4*)(vbaseP + (size_t)(kb + lk) * HD + c0);
                *(float4*)&Vs[lk*PADW + c0] = vv;
            }
        }
        __syncthreads();

        float s[4][4];
        #pragma unroll
        for (int i = 0; i < 4; i++)
            #pragma unroll
            for (int j = 0; j < 4; j++) s[i][j] = 0.f;
        #pragma unroll 8
        for (int c = 0; c < 64; c++) {
            float4 a = *(const float4*)&Qs[c*PADW + ty*4];
            float4 bk = *(const float4*)&Ks[c*PADW + tx*4];
            float av[4] = {a.x, a.y, a.z, a.w};
            float bv[4] = {bk.x, bk.y, bk.z, bk.w};
            #pragma unroll
            for (int i = 0; i < 4; i++)
                #pragma unroll
                for (int j = 0; j < 4; j++)
                    s[i][j] += av[i] * bv[j];
        }

        #pragma unroll
        for (int j = 0; j < 4; j++) {
            int gk = kb + tx*4 + j;
            if (gk < SEQ) {
                int kt = gk / (QHH * QW);
                int rem = gk - kt * (QHH * QW);
                int khh = rem / QW;
                int kww = rem - khh * QW;
                #pragma unroll
                for (int i = 0; i < 4; i++) {
                    int lq = ty*4 + i;
                    s[i][j] = s[i][j] * scale + sbt[lq*8 + kt] + sbh[lq*14 + khh] + sbw[lq*14 + kww];
                }
            } else {
                #pragma unroll
                for (int i = 0; i < 4; i++) s[i][j] = -1e30f;
            }
        }

        #pragma unroll
        for (int i = 0; i < 4; i++) {
            float rm = fmaxf(fmaxf(s[i][0], s[i][1]), fmaxf(s[i][2], s[i][3]));
            #pragma unroll
            for (int off = 8; off; off >>= 1)
                rm = fmaxf(rm, __shfl_xor_sync(0xffffffffu, rm, off));
            float mnew = fmaxf(mrow[i], rm);
            float corr = __expf(mrow[i] - mnew);
            mrow[i] = mnew;
            lrow[i] *= corr;
            #pragma unroll
            for (int j = 0; j < 4; j++) accO[i][j] *= corr;
            float p0 = __expf(s[i][0] - mnew);
            float p1 = __expf(s[i][1] - mnew);
            float p2 = __expf(s[i][2] - mnew);
            float p3 = __expf(s[i][3] - mnew);
            float rs = p0 + p1 + p2 + p3;
            #pragma unroll
            for (int off = 8; off; off >>= 1)
                rs += __shfl_xor_sync(0xffffffffu, rs, off);
            lrow[i] += rs;
            *(float4*)&Ps[(ty*4+i)*PADW + tx*4] = make_float4(p0, p1, p2, p3);
        }
        __syncthreads();

        #pragma unroll 8
        for (int k = 0; k < 64; k++) {
            float4 bv4 = *(const float4*)&Vs[k*PADW + tx*4];
            float bv[4] = {bv4.x, bv4.y, bv4.z, bv4.w};
            float av[4];
            #pragma unroll
            for (int i = 0; i < 4; i++) av[i] = Ps[(ty*4+i)*PADW + k];
            #pragma unroll
            for (int i = 0; i < 4; i++)
                #pragma unroll
                for (int j = 0; j < 4; j++)
                    accO[i][j] += av[i] * bv[j];
        }
        __syncthreads();
    }

    #pragma unroll
    for (int i = 0; i < 4; i++) {
        int gq = qbase + ty*4 + i;
        if (gq >= SEQ) continue;
        float inv = 1.f / lrow[i];
        float4 o = make_float4(accO[i][0]*inv, accO[i][1]*inv, accO[i][2]*inv, accO[i][3]*inv);
        *(float4*)(out + ((size_t)b * SEQ + gq) * DIM + n * HD + tx*4) = o;
    }
}

// ---------------- launch ------------------------------------------------------
extern "C" void kernel_launch(void* const* d_in, const int* in_sizes, int n_in,
                              void* d_out, int out_size)
{
    (void)in_sizes; (void)n_in; (void)out_size;
    const float* q   = (const float*)d_in[0];
    const float* k   = (const float*)d_in[1];
    const float* Wq  = (const float*)d_in[2];
    const float* bq  = (const float*)d_in[3];
    const float* Wk  = (const float*)d_in[4];
    const float* bk  = (const float*)d_in[5];
    const float* Wv  = (const float*)d_in[6];
    const float* bv  = (const float*)d_in[7];
    const float* Wo  = (const float*)d_in[8];
    const float* bo  = (const float*)d_in[9];
    const float* rpt = (const float*)d_in[10];
    const float* rph = (const float*)d_in[11];
    const float* rpw = (const float*)d_in[12];
    float* out = (float*)d_out;

    float *p_qh, *p_kh, *p_vh, *p_attn;
    cudaGetSymbolAddress((void**)&p_qh,   g_qh);
    cudaGetSymbolAddress((void**)&p_kh,   g_kh);
    cudaGetSymbolAddress((void**)&p_vh,   g_vh);
    cudaGetSymbolAddress((void**)&p_attn, g_attn);

    static int smem_set = 0;
    const int attn_smem = (4*64*PADW + 64*36) * 4;
    if (!smem_set) {
        cudaFuncSetAttribute(attn_kernel,
                             cudaFuncAttributeMaxDynamicSharedMemorySize, attn_smem);
        cudaFuncSetAttribute(gemm_mma,
                             cudaFuncAttributeMaxDynamicSharedMemorySize, GEMM_SMEM);
        smem_set = 1;
    }

    dim3 gemmGrid(DIM / 128, (MROWS + 127) / 128);   // 6 x 25
    gemm_mma<<<gemmGrid, 256, GEMM_SMEM>>>(q, Wq, bq, p_qh, MROWS, 1);
    gemm_mma<<<gemmGrid, 256, GEMM_SMEM>>>(k, Wk, bk, p_kh, MROWS, 1);
    gemm_mma<<<gemmGrid, 256, GEMM_SMEM>>>(k, Wv, bv, p_vh, MROWS, 1);

    dim3 attnGrid((SEQ + 63) / 64, NH, BATCH);       // 25 x 12 x 2
    attn_kernel<<<attnGrid, 256, attn_smem>>>(p_qh, p_kh, p_vh, rpt, rph, rpw, p_attn);

    gemm_mma<<<gemmGrid, 256, GEMM_SMEM>>>(p_attn, Wo, bo, out, MROWS, 0);
}

// round 5
// speedup vs baseline: 9.3345x; 1.3193x over previous
#include <cuda_runtime.h>
#include <cstdint>
#include <math.h>

#define BATCH 2
#define NH    12
#define HD    64
#define DIM   768
#define QT    8
#define QHH   14
#define QW    14
#define SEQ   1568
#define KSEQ  1600
#define MROWS 3136

// ---------------- scratch ------------------------------------------------------
__device__ float g_qh[BATCH*NH*KSEQ*HD];
__device__ float g_kh[BATCH*NH*KSEQ*HD];
__device__ float g_vh[BATCH*NH*KSEQ*HD];
__device__ float g_attn[MROWS*DIM];

// ---------------- mma.sync helpers --------------------------------------------
__device__ __forceinline__ uint32_t f2tf32(float x) {
    uint32_t r;
    asm("cvt.rna.tf32.f32 %0, %1;" : "=r"(r) : "f"(x));
    return r;
}
__device__ __forceinline__ void mma_tf32(float* c, const uint32_t* a, const uint32_t* b) {
    asm volatile(
        "mma.sync.aligned.m16n8k8.row.col.f32.tf32.tf32.f32 "
        "{%0,%1,%2,%3}, {%4,%5,%6,%7}, {%8,%9}, {%0,%1,%2,%3};"
        : "+f"(c[0]), "+f"(c[1]), "+f"(c[2]), "+f"(c[3])
        : "r"(a[0]), "r"(a[1]), "r"(a[2]), "r"(a[3]), "r"(b[0]), "r"(b[1]));
}

// ---------------- tf32 mma GEMM (unchanged from round 4) ----------------------
#define KC 32
#define LDT 36
#define EPI_PITCH 132
#define GEMM_SMEM (128 * EPI_PITCH * 4)

__global__ __launch_bounds__(256)
void gemm_mma(const float* __restrict__ A, const float* __restrict__ W,
              const float* __restrict__ bias, float* __restrict__ dst,
              int M, int headMode)
{
    extern __shared__ float smf[];
    uint32_t* As = (uint32_t*)smf;
    uint32_t* Bs = As + 128 * LDT;

    const int tid = threadIdx.x;
    const int lane = tid & 31;
    const int wid = tid >> 5;
    const int wm = wid >> 2;
    const int wn = wid & 3;
    const int rowBlk = blockIdx.y * 128;
    const int colBlk = blockIdx.x * 128;

    float acc[4][4][4];
    #pragma unroll
    for (int mi = 0; mi < 4; mi++)
        #pragma unroll
        for (int ni = 0; ni < 4; ni++)
            #pragma unroll
            for (int e = 0; e < 4; e++) acc[mi][ni][e] = 0.f;

    const int lrow = tid >> 1;
    const int lc0 = (tid & 1) * 16;
    const bool avalid = (rowBlk + lrow) < M;
    const float* aptr = A + (size_t)(rowBlk + lrow) * DIM + lc0;
    const float* wptr = W + (size_t)(colBlk + lrow) * DIM + lc0;

    float4 ra[4], rb[4];
    #pragma unroll
    for (int i = 0; i < 4; i++) {
        ra[i] = avalid ? *(const float4*)(aptr + i * 4) : make_float4(0,0,0,0);
        rb[i] = *(const float4*)(wptr + i * 4);
    }

    const int NCH = DIM / KC;
    for (int ch = 0; ch < NCH; ch++) {
        if (ch > 0) __syncthreads();
        #pragma unroll
        for (int i = 0; i < 4; i++) {
            uint4 ua = make_uint4(f2tf32(ra[i].x), f2tf32(ra[i].y), f2tf32(ra[i].z), f2tf32(ra[i].w));
            uint4 ub = make_uint4(f2tf32(rb[i].x), f2tf32(rb[i].y), f2tf32(rb[i].z), f2tf32(rb[i].w));
            *(uint4*)&As[lrow * LDT + lc0 + i * 4] = ua;
            *(uint4*)&Bs[lrow * LDT + lc0 + i * 4] = ub;
        }
        __syncthreads();
        if (ch + 1 < NCH) {
            const int k0 = (ch + 1) * KC;
            #pragma unroll
            for (int i = 0; i < 4; i++) {
                ra[i] = avalid ? *(const float4*)(aptr + k0 + i * 4) : make_float4(0,0,0,0);
                rb[i] = *(const float4*)(wptr + k0 + i * 4);
            }
        }
        #pragma unroll
        for (int ks = 0; ks < 4; ks++) {
            const int c0 = ks * 8 + (lane & 3);
            uint32_t afr[4][4], bfr[4][2];
            #pragma unroll
            for (int mi = 0; mi < 4; mi++) {
                const int r = wm * 64 + mi * 16 + (lane >> 2);
                afr[mi][0] = As[r * LDT + c0];
                afr[mi][1] = As[(r + 8) * LDT + c0];
                afr[mi][2] = As[r * LDT + c0 + 4];
                afr[mi][3] = As[(r + 8) * LDT + c0 + 4];
            }
            #pragma unroll
            for (int ni = 0; ni < 4; ni++) {
                const int bn = wn * 32 + ni * 8 + (lane >> 2);
                bfr[ni][0] = Bs[bn * LDT + c0];
                bfr[ni][1] = Bs[bn * LDT + c0 + 4];
            }
            #pragma unroll
            for (int mi = 0; mi < 4; mi++)
                #pragma unroll
                for (int ni = 0; ni < 4; ni++)
                    mma_tf32(acc[mi][ni], afr[mi], bfr[ni]);
        }
    }
    __syncthreads();

    float* epi = smf;
    #pragma unroll
    for (int mi = 0; mi < 4; mi++) {
        const int r = wm * 64 + mi * 16 + (lane >> 2);
        #pragma unroll
        for (int ni = 0; ni < 4; ni++) {
            const int c = wn * 32 + ni * 8 + 2 * (lane & 3);
            *(float2*)&epi[r * EPI_PITCH + c]       = make_float2(acc[mi][ni][0], acc[mi][ni][1]);
            *(float2*)&epi[(r + 8) * EPI_PITCH + c] = make_float2(acc[mi][ni][2], acc[mi][ni][3]);
        }
    }
    __syncthreads();

    for (int it = tid; it < 128 * 32; it += 256) {
        const int m2 = it >> 5;
        const int gm = rowBlk + m2;
        if (gm >= M) continue;
        const int c4 = (it & 31) * 4;
        const float4 bv = *(const float4*)(bias + colBlk + c4);
        float4 v;
        v.x = epi[m2 * EPI_PITCH + c4 + 0] + bv.x;
        v.y = epi[m2 * EPI_PITCH + c4 + 1] + bv.y;
        v.z = epi[m2 * EPI_PITCH + c4 + 2] + bv.z;
        v.w = epi[m2 * EPI_PITCH + c4 + 3] + bv.w;
        const int o = colBlk + c4;
        if (headMode) {
            int b = gm / SEQ;
            int pos = gm - b * SEQ;
            int n = o >> 6, c = o & 63;
            *(float4*)(dst + (((size_t)(b * NH + n)) * KSEQ + pos) * HD + c) = v;
        } else {
            *(float4*)(dst + (size_t)gm * DIM + o) = v;
        }
    }
}

// ---------------- tensor-core flash attention ---------------------------------
// grid (25, 12, 2), 128 threads (4 warps; warp = 16 q-rows x all 64 cols)
#define LDK 68
#define ATTN_SMEM ((3 * 64 * LDK + 64 * 36) * 4)   // 61440 B

__global__ __launch_bounds__(128)
void attn_mma(const float* __restrict__ qh, const float* __restrict__ kh,
              const float* __restrict__ vh,
              const float* __restrict__ rpt, const float* __restrict__ rph,
              const float* __restrict__ rpw,
              float* __restrict__ out)
{
    extern __shared__ float sm[];
    float*    Qs = sm;                                // [c][q] floats; reused as Ps [q][k] tf32
    uint32_t* Ks = (uint32_t*)(sm + 64 * LDK);        // [k][c] tf32
    uint32_t* Vt = Ks + 64 * LDK;                     // [c][k] tf32
    float*   sbt = (float*)(Vt + 64 * LDK);           // [64][8]
    float*   sbh = sbt + 64 * 8;                      // [64][14]
    float*   sbw = sbh + 64 * 14;                     // [64][14]
    uint32_t* Ps = (uint32_t*)Qs;

    const int tid = threadIdx.x;
    const int lane = tid & 31;
    const int wid = tid >> 5;                         // 0..3
    const int qblk = blockIdx.x;
    const int n = blockIdx.y;
    const int b = blockIdx.z;
    const int bn = b * NH + n;
    const int qbase = qblk * 64;

    const float* qbaseP = qh + (size_t)bn * KSEQ * HD;
    const float* kbaseP = kh + (size_t)bn * KSEQ * HD;
    const float* vbaseP = vh + (size_t)bn * KSEQ * HD;

    // ---- load Q tile transposed [c][q] (fp32, for bias dots + fragments) ----
    {
        const int tx = tid & 15;            // c group
        const int ty = tid >> 4;            // 0..7
        const int c0 = tx * 4;
        #pragma unroll
        for (int it = 0; it < 8; it++) {
            int lq = ty + 8 * it;
            int gq = qbase + lq;
            float4 v = make_float4(0,0,0,0);
            if (gq < SEQ) v = *(const float4*)(qbaseP + (size_t)gq * HD + c0);
            Qs[(c0+0)*LDK + lq] = v.x;
            Qs[(c0+1)*LDK + lq] = v.y;
            Qs[(c0+2)*LDK + lq] = v.z;
            Qs[(c0+3)*LDK + lq] = v.w;
        }
    }
    __syncthreads();

    // ---- bias tables ----
    for (int idx = tid; idx < 64 * 36; idx += 128) {
        int lq = idx & 63;
        int j  = idx >> 6;
        int gq = qbase + lq;
        if (gq >= SEQ) gq = SEQ - 1;
        int t = gq / (QHH * QW);
        int rem = gq - t * (QHH * QW);
        int h = rem / QW;
        int w = rem - h * QW;
        const float* r;
        float* dstp;
        if (j < 8)       { r = rpt + (size_t)(t - j + QT - 1) * HD;              dstp = &sbt[lq*8 + j]; }
        else if (j < 22) { int kk = j - 8;  r = rph + (size_t)(h - kk + QHH - 1) * HD; dstp = &sbh[lq*14 + kk]; }
        else             { int kk = j - 22; r = rpw + (size_t)(w - kk + QW  - 1) * HD; dstp = &sbw[lq*14 + kk]; }
        float acc = 0.f;
        #pragma unroll
        for (int c = 0; c < HD; c++) acc += Qs[c*LDK + lq] * r[c];
        *dstp = acc;
    }
    __syncthreads();

    // ---- Q fragments (tf32, registers) ----
    const int r0 = wid * 16 + (lane >> 2);
    uint32_t qa[8][4];
    #pragma unroll
    for (int ks = 0; ks < 8; ks++) {
        const int c0 = ks * 8 + (lane & 3);
        qa[ks][0] = f2tf32(Qs[c0*LDK + r0]);
        qa[ks][1] = f2tf32(Qs[c0*LDK + r0 + 8]);
        qa[ks][2] = f2tf32(Qs[(c0+4)*LDK + r0]);
        qa[ks][3] = f2tf32(Qs[(c0+4)*LDK + r0 + 8]);
    }
    __syncthreads();   // everyone done reading Qs -> reusable as Ps

    float accO[8][4];
    #pragma unroll
    for (int nb = 0; nb < 8; nb++)
        #pragma unroll
        for (int e = 0; e < 4; e++) accO[nb][e] = 0.f;
    float m0 = -1e30f, m1 = -1e30f, l0 = 0.f, l1 = 0.f;

    const float scale = 0.125f;
    const int lkrow = tid >> 1;
    const int lhalf = (tid & 1) * 32;

    for (int kb = 0; kb < KSEQ; kb += 64) {
        // ---- fill Ks [k][c] and Vt [c][k] (tf32) ----
        {
            const float* kr = kbaseP + (size_t)(kb + lkrow) * HD + lhalf;
            const float* vr = vbaseP + (size_t)(kb + lkrow) * HD + lhalf;
            #pragma unroll
            for (int i = 0; i < 8; i++) {
                float4 kv = *(const float4*)(kr + i * 4);
                *(uint4*)&Ks[lkrow*LDK + lhalf + i*4] =
                    make_uint4(f2tf32(kv.x), f2tf32(kv.y), f2tf32(kv.z), f2tf32(kv.w));
                float4 vv = *(const float4*)(vr + i * 4);
                const int cb = lhalf + i * 4;
                Vt[(cb+0)*LDK + lkrow] = f2tf32(vv.x);
                Vt[(cb+1)*LDK + lkrow] = f2tf32(vv.y);
                Vt[(cb+2)*LDK + lkrow] = f2tf32(vv.z);
                Vt[(cb+3)*LDK + lkrow] = f2tf32(vv.w);
            }
        }
        __syncthreads();

        // ---- S = Q K^T ----
        float sc[8][4];
        #pragma unroll
        for (int nb = 0; nb < 8; nb++)
            #pragma unroll
            for (int e = 0; e < 4; e++) sc[nb][e] = 0.f;
        #pragma unroll
        for (int ks = 0; ks < 8; ks++) {
            const int c0 = ks * 8 + (lane & 3);
            #pragma unroll
            for (int nb = 0; nb < 8; nb++) {
                uint32_t bfr[2];
                bfr[0] = Ks[(nb*8 + (lane >> 2))*LDK + c0];
                bfr[1] = Ks[(nb*8 + (lane >> 2))*LDK + c0 + 4];
                mma_tf32(sc[nb], qa[ks], bfr);
            }
        }

        // ---- scale + bias + mask ----
        #pragma unroll
        for (int nb = 0; nb < 8; nb++) {
            const int col0 = nb * 8 + 2 * (lane & 3);
            #pragma unroll
            for (int j = 0; j < 2; j++) {
                const int gk = kb + col0 + j;
                if (gk < SEQ) {
                    int kt = gk / (QHH * QW);
                    int rem = gk - kt * (QHH * QW);
                    int khh = rem / QW;
                    int kww = rem - khh * QW;
                    sc[nb][j]   = sc[nb][j]   * scale + sbt[r0*8 + kt]     + sbh[r0*14 + khh]     + sbw[r0*14 + kww];
                    sc[nb][j+2] = sc[nb][j+2] * scale + sbt[(r0+8)*8 + kt] + sbh[(r0+8)*14 + khh] + sbw[(r0+8)*14 + kww];
                } else {
                    sc[nb][j] = -1e30f;
                    sc[nb][j+2] = -1e30f;
                }
            }
        }

        // ---- online softmax (thread owns 2 full rows, quad-shuffle reduce) ----
        float rm0 = -1e30f, rm1 = -1e30f;
        #pragma unroll
        for (int nb = 0; nb < 8; nb++) {
            rm0 = fmaxf(rm0, fmaxf(sc[nb][0], sc[nb][1]));
            rm1 = fmaxf(rm1, fmaxf(sc[nb][2], sc[nb][3]));
        }
        rm0 = fmaxf(rm0, __shfl_xor_sync(0xffffffffu, rm0, 1));
        rm0 = fmaxf(rm0, __shfl_xor_sync(0xffffffffu, rm0, 2));
        rm1 = fmaxf(rm1, __shfl_xor_sync(0xffffffffu, rm1, 1));
        rm1 = fmaxf(rm1, __shfl_xor_sync(0xffffffffu, rm1, 2));

        const float mn0 = fmaxf(m0, rm0);
        const float mn1 = fmaxf(m1, rm1);
        const float cor0 = __expf(m0 - mn0);
        const float cor1 = __expf(m1 - mn1);
        m0 = mn0; m1 = mn1;
        l0 *= cor0; l1 *= cor1;
        #pragma unroll
        for (int nb = 0; nb < 8; nb++) {
            accO[nb][0] *= cor0; accO[nb][1] *= cor0;
            accO[nb][2] *= cor1; accO[nb][3] *= cor1;
        }

        float rs0 = 0.f, rs1 = 0.f;
        #pragma unroll
        for (int nb = 0; nb < 8; nb++) {
            float e0 = __expf(sc[nb][0] - mn0);
            float e1 = __expf(sc[nb][1] - mn0);
            float e2 = __expf(sc[nb][2] - mn1);
            float e3 = __expf(sc[nb][3] - mn1);
            rs0 += e0 + e1;
            rs1 += e2 + e3;
            const int col0 = nb * 8 + 2 * (lane & 3);
            *(uint2*)&Ps[r0*LDK + col0]       = make_uint2(f2tf32(e0), f2tf32(e1));
            *(uint2*)&Ps[(r0+8)*LDK + col0]   = make_uint2(f2tf32(e2), f2tf32(e3));
        }
        rs0 += __shfl_xor_sync(0xffffffffu, rs0, 1);
        rs0 += __shfl_xor_sync(0xffffffffu, rs0, 2);
        rs1 += __shfl_xor_sync(0xffffffffu, rs1, 1);
        rs1 += __shfl_xor_sync(0xffffffffu, rs1, 2);
        l0 += rs0; l1 += rs1;

        __syncwarp();   // P rows of this warp visible to whole warp

        // ---- O += P V ----
        #pragma unroll
        for (int ks = 0; ks < 8; ks++) {
            const int kc0 = ks * 8 + (lane & 3);
            uint32_t pa[4];
            pa[0] = Ps[r0*LDK + kc0];
            pa[1] = Ps[(r0+8)*LDK + kc0];
            pa[2] = Ps[r0*LDK + kc0 + 4];
            pa[3] = Ps[(r0+8)*LDK + kc0 + 4];
            #pragma unroll
            for (int nb = 0; nb < 8; nb++) {
                uint32_t bfr[2];
                bfr[0] = Vt[(nb*8 + (lane >> 2))*LDK + kc0];
                bfr[1] = Vt[(nb*8 + (lane >> 2))*LDK + kc0 + 4];
                mma_tf32(accO[nb], pa, bfr);
            }
        }
        __syncthreads();   // done with Ks/Vt before next fill
    }

    // ---- write output ----
    const float inv0 = 1.f / l0;
    const float inv1 = 1.f / l1;
    const int gq0 = qbase + r0;
    const int gq1 = gq0 + 8;
    #pragma unroll
    for (int nb = 0; nb < 8; nb++) {
        const int col0 = n * HD + nb * 8 + 2 * (lane & 3);
        if (gq0 < SEQ)
            *(float2*)(out + ((size_t)b * SEQ + gq0) * DIM + col0) =
                make_float2(accO[nb][0] * inv0, accO[nb][1] * inv0);
        if (gq1 < SEQ)
            *(float2*)(out + ((size_t)b * SEQ + gq1) * DIM + col0) =
                make_float2(accO[nb][2] * inv1, accO[nb][3] * inv1);
    }
}

// ---------------- launch ------------------------------------------------------
extern "C" void kernel_launch(void* const* d_in, const int* in_sizes, int n_in,
                              void* d_out, int out_size)
{
    (void)in_sizes; (void)n_in; (void)out_size;
    const float* q   = (const float*)d_in[0];
    const float* k   = (const float*)d_in[1];
    const float* Wq  = (const float*)d_in[2];
    const float* bq  = (const float*)d_in[3];
    const float* Wk  = (const float*)d_in[4];
    const float* bk  = (const float*)d_in[5];
    const float* Wv  = (const float*)d_in[6];
    const float* bv  = (const float*)d_in[7];
    const float* Wo  = (const float*)d_in[8];
    const float* bo  = (const float*)d_in[9];
    const float* rpt = (const float*)d_in[10];
    const float* rph = (const float*)d_in[11];
    const float* rpw = (const float*)d_in[12];
    float* out = (float*)d_out;

    float *p_qh, *p_kh, *p_vh, *p_attn;
    cudaGetSymbolAddress((void**)&p_qh,   g_qh);
    cudaGetSymbolAddress((void**)&p_kh,   g_kh);
    cudaGetSymbolAddress((void**)&p_vh,   g_vh);
    cudaGetSymbolAddress((void**)&p_attn, g_attn);

    static int smem_set = 0;
    if (!smem_set) {
        cudaFuncSetAttribute(gemm_mma,
                             cudaFuncAttributeMaxDynamicSharedMemorySize, GEMM_SMEM);
        cudaFuncSetAttribute(attn_mma,
                             cudaFuncAttributeMaxDynamicSharedMemorySize, ATTN_SMEM);
        smem_set = 1;
    }

    dim3 gemmGrid(DIM / 128, (MROWS + 127) / 128);   // 6 x 25
    gemm_mma<<<gemmGrid, 256, GEMM_SMEM>>>(q, Wq, bq, p_qh, MROWS, 1);
    gemm_mma<<<gemmGrid, 256, GEMM_SMEM>>>(k, Wk, bk, p_kh, MROWS, 1);
    gemm_mma<<<gemmGrid, 256, GEMM_SMEM>>>(k, Wv, bv, p_vh, MROWS, 1);

    dim3 attnGrid((SEQ + 63) / 64, NH, BATCH);       // 25 x 12 x 2
    attn_mma<<<attnGrid, 128, ATTN_SMEM>>>(p_qh, p_kh, p_vh, rpt, rph, rpw, p_attn);

    gemm_mma<<<gemmGrid, 256, GEMM_SMEM>>>(p_attn, Wo, bo, out, MROWS, 0);
}